// round 16
// baseline (speedup 1.0000x reference)
#include <cuda_runtime.h>
#include <cuda_fp16.h>
#include <cstdint>

#define WIN 1022
#define T_IN 127
#define BATCH 64
#define NF (BATCH * T_IN)       // 8128
#define HOP 256
#define T_OUT 62
#define NF3 (BATCH * T_OUT)     // 3968
#define L_OUT 16670
#define J_EVEN 16608

#define BLOB 16384              // one 128row x 64col fp16 SW128 tile
#define NCH1 8                  // pass1: Ar*Bc (0-3) + Ai*Bs (4-7), hi-only
#define NCH3 16                 // pass3: re = ze*Wc (0-7), im = zo*Ws (8-15), hi-only
#define CH1_BYTES 32768         // A 16K + B 16K
#define CH3_BYTES 24576         // A 16K + B 8K

// ---------------- device scratch ----------------
__device__ __half g_frames[NF * 512];        // fp16 frames (synth folded)
__device__ float  g_tail[BATCH * 32];
__device__ __align__(16) char g_A1cat[64 * 8 * BLOB];    // 8MB: 0-3 Arh | 4-7 Aih
__device__ __align__(16) char g_B1cat[4 * 8 * BLOB];     // 512KB: 0-3 Bch | 4-7 Bsh
__device__ __align__(16) char g_A3cat[31 * 16 * BLOB];   // 8MB: 0-7 zeh | 8-15 zoh
__device__ __align__(16) char g_B3cat[4 * 16 * BLOB];    // 1MB: 0-7 Wch | 8-15 Wsh

// ---------------- helpers ----------------
__device__ __forceinline__ uint32_t smem_to_u32(const void* p) {
    uint32_t a;
    asm("{ .reg .u64 t; cvta.to.shared.u64 t, %1; cvt.u32.u64 %0, t; }" : "=r"(a) : "l"(p));
    return a;
}
__device__ __forceinline__ void cp16(uint32_t saddr, const void* gaddr) {
    asm volatile("cp.async.cg.shared.global [%0], [%1], 16;" :: "r"(saddr), "l"(gaddr));
}
#define CP_COMMIT() asm volatile("cp.async.commit_group;" ::: "memory")
#define CP_WAIT(n)  asm volatile("cp.async.wait_group %0;" :: "n"(n) : "memory")

__device__ __forceinline__ void ldsm_x4(uint32_t& r0, uint32_t& r1, uint32_t& r2, uint32_t& r3, uint32_t addr) {
    asm volatile("ldmatrix.sync.aligned.m8n8.x4.shared.b16 {%0,%1,%2,%3}, [%4];"
                 : "=r"(r0), "=r"(r1), "=r"(r2), "=r"(r3) : "r"(addr));
}
__device__ __forceinline__ void mma16816(float* d, const uint32_t* a, uint32_t b0, uint32_t b1) {
    asm volatile("mma.sync.aligned.m16n8k16.row.col.f32.f16.f16.f32 "
                 "{%0,%1,%2,%3},{%4,%5,%6,%7},{%8,%9},{%0,%1,%2,%3};"
                 : "+f"(d[0]), "+f"(d[1]), "+f"(d[2]), "+f"(d[3])
                 : "r"(a[0]), "r"(a[1]), "r"(a[2]), "r"(a[3]), "r"(b0), "r"(b1));
}
__device__ __forceinline__ unsigned short hb(float x) {
    __half h = __float2half_rn(x);
    return *reinterpret_cast<unsigned short*>(&h);
}
__device__ __forceinline__ int swz(int row, int col) {
    int b = row * 128 + col * 2;
    return b ^ ((b >> 3) & 0x70);
}
__device__ __forceinline__ float hannf(int x) {   // hann window, x in [0,1022)
    return 0.5f - 0.5f * cospif((float)x / 511.0f);
}

// OLA-gather of decimated signal value y[b][j] directly from frames/tail.
__device__ __forceinline__ float ola(int b, int j) {
    if (j < J_EVEN) {
        int p = 2 * j;
        int t_hi = min(126, p >> 8);
        int t_lo = max(0, p - 766) >> 8;
        float acc = 0.0f;
        for (int t = t_lo; t <= t_hi; t++) {
            int m = j - (t << 7);
            acc += __half2float(g_frames[(size_t)(b * 127 + t) * 512 + m]);
        }
        return acc;
    } else {
        int n2 = j - 15648;
        if (n2 & 1) return g_tail[b * 32 + ((n2 - 961) >> 1)];
        return __half2float(g_frames[(size_t)(b * 127 + 126) * 512 + (n2 >> 1)]);
    }
}

// ---------------- fused table fills ----------------
// blocks 0..511: W1 (m = bid); blocks 512..1023: W3 (kb = bid - 512)
__global__ void k_fill() {
    int bid = blockIdx.x;
    if (bid < 512) {
        int m = bid;
        int k = threadIdx.x;       // 0..255
        __shared__ float s_sv;
        if (threadIdx.x == 0) {
            float sv = 0.0f;
            if (m < 511) {
                int i = (2 * m) & 255;
                float d = 0.0f;
#pragma unroll
                for (int q = 0; q < 4; q++) {
                    int x = q * 256 + i;
                    if (x < WIN) { float ww = hannf(x); d += ww * ww; }
                }
                sv = hannf(2 * m) / d;
            }
            s_sv = sv;
        }
        __syncthreads();
        const float invN = 1.0f / 1022.0f;
        float vc = 0.0f, vs = 0.0f;
        if (m < 511) {
            if (k == 0) vc = invN * s_sv;
            else {
                int r = (k * m) % 511;
                float sn, cs;
                sincospif(2.0f * (float)r / 511.0f, &sn, &cs);
                vc = 2.0f * invN * cs * s_sv;
                vs = -2.0f * invN * sn * s_sv;
            }
        }
        char* base = g_B1cat + (size_t)(m >> 7) * 8 * BLOB;
        int chunk = k >> 6, off = swz(m & 127, k & 63);
        *(unsigned short*)(base + (chunk) * BLOB + off) = hb(vc);
        *(unsigned short*)(base + (4 + chunk) * BLOB + off) = hb(vs);
    } else {
        int kb = bid - 512;
        char* base = g_B3cat + (size_t)(kb >> 7) * 16 * BLOB;
        int row = kb & 127;
        for (int n = threadIdx.x; n < 512; n += 256) {
            int j = (n * kb) % WIN;
            float sn, cs;
            sincospif((float)j / 511.0f, &sn, &cs);
            int chunk = n >> 6, off = swz(row, n & 63);
            *(unsigned short*)(base + (chunk) * BLOB + off) = hb(cs);        // Wch
            *(unsigned short*)(base + (8 + chunk) * BLOB + off) = hb(-sn);   // Wsh
        }
    }
}

// ---------------- fold1: spectrum fold, fp16 hi only ----------------
__global__ void k_fold1(const float2* __restrict__ inF2) {
    __shared__ ushort2 tile[32][33];
    int f0 = blockIdx.x * 32;    // 0..8096
    int k0 = blockIdx.y * 32;    // 0..224
    int lx = threadIdx.x & 31, ly = threadIdx.x >> 5;
    int f = f0 + lx;
    int b = f / 127, t = f - b * 127;
#pragma unroll
    for (int q = 0; q < 4; q++) {
        int k = k0 + ly + 8 * q;
        float2 x0 = inF2[(b * 512 + k) * 127 + t];
        float2 x1 = inF2[(b * 512 + 511 - k) * 127 + t];
        ushort2 v;
        v.x = hb(x0.x + x1.x);   // Arh
        v.y = hb(x0.y - x1.y);   // Aih
        tile[ly + 8 * q][lx] = v;
    }
    __syncthreads();
    char* base = g_A1cat + (size_t)(f0 >> 7) * 8 * BLOB;
    int row0 = f0 & 127;
    int kk = k0 + lx;
    int chunk = kk >> 6, col = kk & 63;
#pragma unroll
    for (int q = 0; q < 4; q++) {
        int fl = ly + 8 * q;
        ushort2 v = tile[lx][fl];
        int off = swz(row0 + fl, col);
        *(unsigned short*)(base + (chunk) * BLOB + off) = v.x;
        *(unsigned short*)(base + (4 + chunk) * BLOB + off) = v.y;
    }
}

// ---------------- GEMM 1: frames[f][m], M=128 f x N=128 m, depth-3 pipeline ----------------
__global__ void __launch_bounds__(256, 2) k_mma1() {
    extern __shared__ char smem[];
    uint32_t sb = smem_to_u32(smem);
    int tid = threadIdx.x, lane = tid & 31, wid = tid >> 5;
    int wm = wid >> 2, wn = wid & 3;
    int ntile = blockIdx.x;      // m tile 0..3
    int ftile = blockIdx.y;      // f tile 0..63
    const char* Ab = g_A1cat + (size_t)ftile * 8 * BLOB;
    const char* Bb = g_B1cat + (size_t)ntile * 8 * BLOB;

    float acc[4][4][4];
#pragma unroll
    for (int i = 0; i < 4; i++)
#pragma unroll
        for (int j = 0; j < 4; j++)
#pragma unroll
            for (int e = 0; e < 4; e++) acc[i][j][e] = 0.0f;

#define STAGE1(c) do { \
        uint32_t d = sb + ((c) % 3) * CH1_BYTES; \
        const char* ga = Ab + (size_t)(c) * BLOB; \
        const char* gb = Bb + (size_t)(c) * BLOB; \
        _Pragma("unroll") \
        for (int r = 0; r < 4; r++) { \
            int e = tid + 256 * r; \
            cp16(d + e * 16, ga + e * 16); \
            cp16(d + 16384 + e * 16, gb + e * 16); \
        } \
        CP_COMMIT(); \
    } while (0)

    STAGE1(0); STAGE1(1);
    int S = 2;
    for (int c = 0; c < NCH1; c++) {
        if (S < NCH1) { STAGE1(S); S++; }
        int pend = S - 1 - c;
        if (pend >= 2) CP_WAIT(2); else if (pend == 1) CP_WAIT(1); else CP_WAIT(0);
        __syncthreads();
        uint32_t SA = sb + (c % 3) * CH1_BYTES, SB = SA + 16384;
#pragma unroll
        for (int k0 = 0; k0 < 64; k0 += 16) {
            uint32_t af[4][4], bf[2][4];
            int colu = k0 + ((lane >> 4) << 3);
#pragma unroll
            for (int i = 0; i < 4; i++) {
                int row = wm * 64 + i * 16 + (lane & 15);
                ldsm_x4(af[i][0], af[i][1], af[i][2], af[i][3], SA + swz(row, colu));
            }
#pragma unroll
            for (int j2 = 0; j2 < 2; j2++) {
                int row = wn * 32 + j2 * 16 + (lane & 15);
                ldsm_x4(bf[j2][0], bf[j2][1], bf[j2][2], bf[j2][3], SB + swz(row, colu));
            }
#pragma unroll
            for (int i = 0; i < 4; i++)
#pragma unroll
                for (int j = 0; j < 4; j++)
                    mma16816(acc[i][j], af[i], bf[j >> 1][j & 1], bf[j >> 1][(j & 1) + 2]);
        }
        __syncthreads();
    }
    int g = lane >> 2, t4 = lane & 3;
#pragma unroll
    for (int i = 0; i < 4; i++) {
        int f0 = ftile * 128 + wm * 64 + i * 16 + g;
#pragma unroll
        for (int j = 0; j < 4; j++) {
            int col = ntile * 128 + wn * 32 + j * 8 + t4 * 2;
            if (f0 < NF)
                *(__half2*)(g_frames + (size_t)f0 * 512 + col) = __floats2half2_rn(acc[i][j][0], acc[i][j][1]);
            if (f0 + 8 < NF)
                *(__half2*)(g_frames + (size_t)(f0 + 8) * 512 + col) = __floats2half2_rn(acc[i][j][2], acc[i][j][3]);
        }
    }
}

// ---------------- pass 1b: odd tail of frame 126 (rotation recurrence, 512 thr) ----------------
__global__ void k_pass1b(const float2* __restrict__ inF2) {
    __shared__ float2 sbuf[512];
    __shared__ float part[31][16];
    int b = blockIdx.x;
    int tid = threadIdx.x;   // 512 threads
    if (tid < 512)
        sbuf[tid] = inF2[(b * 512 + tid) * 127 + 126];
    __syncthreads();
    int ni = tid >> 4, kp = tid & 15;
    if (ni < 31) {
        int n = 961 + 2 * ni;
        float c, s, cs, ss;
        sincospif((float)((n * kp) % WIN) / 511.0f, &s, &c);
        sincospif((float)((16 * n) % WIN) / 511.0f, &ss, &cs);
        float acc = 0.0f;
#pragma unroll 8
        for (int it = 0; it < 32; it++) {
            float2 x = sbuf[kp + 16 * it];
            acc += 2.0f * (x.x * c - x.y * s);
            float c2 = c * cs - s * ss;
            s = c * ss + s * cs;
            c = c2;
        }
        if (kp == 0) acc -= sbuf[0].x;
        if (kp == 15) acc += sbuf[511].x;
        part[ni][kp] = acc;
    }
    __syncthreads();
    if (tid < 31) {
        float sum = 0.0f;
#pragma unroll
        for (int q = 0; q < 16; q++) sum += part[tid][q];
        int np = 961 + 2 * tid;
        int i = np & 255;
        float d = 0.0f;
#pragma unroll
        for (int q = 0; q < 4; q++) {
            int x = q * 256 + i;
            if (x < WIN) { float ww = hannf(x); d += ww * ww; }
        }
        g_tail[b * 32 + tid] = sum * (1.0f / 1022.0f) * (hannf(np) / d);
    }
}

// ---------------- fold3 (fused OLA): window + symmetry fold, gather y inline ----------------
__global__ void k_fold3() {
    int f0 = blockIdx.x * 32;    // 0..3936
    int n0 = blockIdx.y * 32;    // 0..480
    int lx = threadIdx.x & 31, ly = threadIdx.x >> 5;
    int n = n0 + lx;
    float w = hannf(n);
    bool hasp = (n >= 1 && n <= 510);
    char* base = g_A3cat + (size_t)(f0 >> 7) * 16 * BLOB;
    int row0 = f0 & 127;
    int chunk = n >> 6, col = n & 63;
#pragma unroll
    for (int q = 0; q < 4; q++) {
        int fl = ly + 8 * q;
        int f = f0 + fl;
        int b = f / 62, t = f - b * 62;
        int jbase = t * 256;
        float y = ola(b, jbase + n);
        float yp = hasp ? ola(b, jbase + 1022 - n) : 0.0f;
        int off = swz(row0 + fl, col);
        *(unsigned short*)(base + (chunk) * BLOB + off) = hb(w * (y + yp));      // zeh
        *(unsigned short*)(base + (8 + chunk) * BLOB + off) = hb(w * (y - yp));  // zoh
    }
}

// ---------------- GEMM 3: S[k][f], M=128 k x N=64 f, depth-3 pipeline ----------------
__global__ void __launch_bounds__(256, 2) k_mma3(float2* __restrict__ outF2) {
    extern __shared__ char smem[];
    uint32_t sb = smem_to_u32(smem);
    int tid = threadIdx.x, lane = tid & 31, wid = tid >> 5;
    int wm = wid >> 1, wn = wid & 1;     // 4 x 2 warps
    int ftile = blockIdx.x;      // f tile 0..61 (64 frames each)
    int ktile = blockIdx.y;      // k tile 0..3
    const char* Ab = g_B3cat + (size_t)ktile * 16 * BLOB;        // W blobs: 0-7 Wch, 8-15 Wsh
    const char* Bb = g_A3cat + (size_t)(ftile >> 1) * 16 * BLOB; // z blobs: 0-7 zeh, 8-15 zoh
    int halfoff = (ftile & 1) * 8192;

    float acc[2][4][4], sv[2][4][4];
#pragma unroll
    for (int i = 0; i < 2; i++)
#pragma unroll
        for (int j = 0; j < 4; j++)
#pragma unroll
            for (int e = 0; e < 4; e++) acc[i][j][e] = 0.0f;

#define STAGE3(c) do { \
        uint32_t d = sb + ((c) % 3) * CH3_BYTES; \
        const char* ga = Ab + (size_t)(c) * BLOB; \
        const char* gb = Bb + (size_t)(c) * BLOB + halfoff; \
        _Pragma("unroll") \
        for (int r = 0; r < 4; r++) { \
            int e = tid + 256 * r; \
            cp16(d + e * 16, ga + e * 16); \
        } \
        _Pragma("unroll") \
        for (int r = 0; r < 2; r++) { \
            int e = tid + 256 * r; \
            cp16(d + 16384 + e * 16, gb + e * 16); \
        } \
        CP_COMMIT(); \
    } while (0)

    STAGE3(0); STAGE3(1);
    int S = 2;
    for (int c = 0; c < NCH3; c++) {
        if (S < NCH3) { STAGE3(S); S++; }
        int pend = S - 1 - c;
        if (pend >= 2) CP_WAIT(2); else if (pend == 1) CP_WAIT(1); else CP_WAIT(0);
        __syncthreads();
        uint32_t SA = sb + (c % 3) * CH3_BYTES, SB = SA + 16384;
#pragma unroll
        for (int k0 = 0; k0 < 64; k0 += 16) {
            uint32_t af[2][4], bf[2][4];
            int colu = k0 + ((lane >> 4) << 3);
#pragma unroll
            for (int i = 0; i < 2; i++) {
                int row = wm * 32 + i * 16 + (lane & 15);
                ldsm_x4(af[i][0], af[i][1], af[i][2], af[i][3], SA + swz(row, colu));
            }
#pragma unroll
            for (int j2 = 0; j2 < 2; j2++) {
                int row = wn * 32 + j2 * 16 + (lane & 15);
                ldsm_x4(bf[j2][0], bf[j2][1], bf[j2][2], bf[j2][3], SB + swz(row, colu));
            }
#pragma unroll
            for (int i = 0; i < 2; i++)
#pragma unroll
                for (int j = 0; j < 4; j++)
                    mma16816(acc[i][j], af[i], bf[j >> 1][j & 1], bf[j >> 1][(j & 1) + 2]);
        }
        __syncthreads();
        if (c == 7) {   // end of re chain
#pragma unroll
            for (int i = 0; i < 2; i++)
#pragma unroll
                for (int j = 0; j < 4; j++)
#pragma unroll
                    for (int e = 0; e < 4; e++) { sv[i][j][e] = acc[i][j][e]; acc[i][j][e] = 0.0f; }
        }
    }
    int g = lane >> 2, t4 = lane & 3;
#pragma unroll
    for (int i = 0; i < 2; i++) {
        int kb = ktile * 128 + wm * 32 + i * 16 + g;
#pragma unroll
        for (int j = 0; j < 4; j++) {
            int fc = ftile * 64 + wn * 32 + j * 8 + t4 * 2;
            int b0 = fc / 62, t0 = fc - b0 * 62;
            int b1 = (fc + 1) / 62, t1 = fc + 1 - b1 * 62;
            outF2[((size_t)b0 * 512 + kb) * 62 + t0] = make_float2(sv[i][j][0], acc[i][j][0]);
            outF2[((size_t)b1 * 512 + kb) * 62 + t1] = make_float2(sv[i][j][1], acc[i][j][1]);
            outF2[((size_t)b0 * 512 + kb + 8) * 62 + t0] = make_float2(sv[i][j][2], acc[i][j][2]);
            outF2[((size_t)b1 * 512 + kb + 8) * 62 + t1] = make_float2(sv[i][j][3], acc[i][j][3]);
        }
    }
}

// ---------------- stream/event infra (host objects, created once at load) ----------------
static cudaStream_t g_s1, g_s2;
static cudaEvent_t g_evFork, g_evJoin1, g_evJoin2;
namespace {
struct StreamInit {
    StreamInit() {
        cudaStreamCreateWithFlags(&g_s1, cudaStreamNonBlocking);
        cudaStreamCreateWithFlags(&g_s2, cudaStreamNonBlocking);
        cudaEventCreateWithFlags(&g_evFork, cudaEventDisableTiming);
        cudaEventCreateWithFlags(&g_evJoin1, cudaEventDisableTiming);
        cudaEventCreateWithFlags(&g_evJoin2, cudaEventDisableTiming);
    }
};
static StreamInit g_streamInit;
}

// ---------------- launch ----------------
extern "C" void kernel_launch(void* const* d_in, const int* in_sizes, int n_in,
                              void* d_out, int out_size) {
    (void)in_sizes; (void)n_in; (void)out_size;
    const float2* inF2 = (const float2*)d_in[0];
    float2* outF2 = (float2*)d_out;

    cudaFuncSetAttribute(k_mma1, cudaFuncAttributeMaxDynamicSharedMemorySize, 3 * CH1_BYTES);
    cudaFuncSetAttribute(k_mma3, cudaFuncAttributeMaxDynamicSharedMemorySize, 3 * CH3_BYTES);

    // fork: fill on s1, pass1b on s2, fold1 on main stream
    cudaEventRecord(g_evFork, 0);
    cudaStreamWaitEvent(g_s1, g_evFork, 0);
    cudaStreamWaitEvent(g_s2, g_evFork, 0);

    k_fill<<<1024, 256, 0, g_s1>>>();
    cudaEventRecord(g_evJoin1, g_s1);

    k_pass1b<<<64, 512, 0, g_s2>>>(inF2);
    cudaEventRecord(g_evJoin2, g_s2);

    k_fold1<<<dim3(254, 8), 256>>>(inF2);

    // join fill before mma1 (needs B1 tables; B3 transitively before mma3)
    cudaStreamWaitEvent(0, g_evJoin1, 0);
    k_mma1<<<dim3(4, 64), 256, 3 * CH1_BYTES>>>();

    // join pass1b before fold3 (fused OLA needs g_tail)
    cudaStreamWaitEvent(0, g_evJoin2, 0);
    k_fold3<<<dim3(124, 16), 256>>>();
    k_mma3<<<dim3(62, 4), 256, 3 * CH3_BYTES>>>(outF2);
}

// round 17
// speedup vs baseline: 1.0966x; 1.0966x over previous
#include <cuda_runtime.h>
#include <cuda_fp16.h>
#include <cstdint>

#define WIN 1022
#define T_IN 127
#define BATCH 64
#define NF (BATCH * T_IN)       // 8128
#define HOP 256
#define T_OUT 62
#define NF3 (BATCH * T_OUT)     // 3968
#define SIG_STRIDE 16672
#define L_OUT 16670
#define J_EVEN 16608

#define BLOB 16384              // one 128row x 64col fp16 SW128 tile
#define NCH1 8                  // pass1: Ar*Bc (0-3) + Ai*Bs (4-7), hi-only
#define NCH3 16                 // pass3: re = ze*Wc (0-7), im = zo*Ws (8-15), hi-only
#define CH1_BYTES 24576         // A 16K + B 8K (half-N tile)
#define CH3_BYTES 24576         // A 16K + B 8K

// ---------------- device scratch ----------------
__device__ __half g_frames[NF * 512];        // fp16 frames (synth folded)
__device__ float  g_tail[BATCH * 32];
__device__ float  g_sig[BATCH * SIG_STRIDE];
__device__ __align__(16) char g_A1cat[64 * 8 * BLOB];    // 8MB: 0-3 Arh | 4-7 Aih
__device__ __align__(16) char g_B1cat[4 * 8 * BLOB];     // 512KB: 0-3 Bch | 4-7 Bsh
__device__ __align__(16) char g_A3cat[31 * 16 * BLOB];   // 8MB: 0-7 zeh | 8-15 zoh
__device__ __align__(16) char g_B3cat[4 * 16 * BLOB];    // 1MB: 0-7 Wch | 8-15 Wsh

// ---------------- helpers ----------------
__device__ __forceinline__ uint32_t smem_to_u32(const void* p) {
    uint32_t a;
    asm("{ .reg .u64 t; cvta.to.shared.u64 t, %1; cvt.u32.u64 %0, t; }" : "=r"(a) : "l"(p));
    return a;
}
__device__ __forceinline__ void cp16(uint32_t saddr, const void* gaddr) {
    asm volatile("cp.async.cg.shared.global [%0], [%1], 16;" :: "r"(saddr), "l"(gaddr));
}
#define CP_COMMIT() asm volatile("cp.async.commit_group;" ::: "memory")
#define CP_WAIT(n)  asm volatile("cp.async.wait_group %0;" :: "n"(n) : "memory")

__device__ __forceinline__ void ldsm_x4(uint32_t& r0, uint32_t& r1, uint32_t& r2, uint32_t& r3, uint32_t addr) {
    asm volatile("ldmatrix.sync.aligned.m8n8.x4.shared.b16 {%0,%1,%2,%3}, [%4];"
                 : "=r"(r0), "=r"(r1), "=r"(r2), "=r"(r3) : "r"(addr));
}
__device__ __forceinline__ void mma16816(float* d, const uint32_t* a, uint32_t b0, uint32_t b1) {
    asm volatile("mma.sync.aligned.m16n8k16.row.col.f32.f16.f16.f32 "
                 "{%0,%1,%2,%3},{%4,%5,%6,%7},{%8,%9},{%0,%1,%2,%3};"
                 : "+f"(d[0]), "+f"(d[1]), "+f"(d[2]), "+f"(d[3])
                 : "r"(a[0]), "r"(a[1]), "r"(a[2]), "r"(a[3]), "r"(b0), "r"(b1));
}
__device__ __forceinline__ unsigned short hb(float x) {
    __half h = __float2half_rn(x);
    return *reinterpret_cast<unsigned short*>(&h);
}
__device__ __forceinline__ int swz(int row, int col) {
    int b = row * 128 + col * 2;
    return b ^ ((b >> 3) & 0x70);
}
__device__ __forceinline__ float hannf(int x) {   // hann window, x in [0,1022)
    return 0.5f - 0.5f * cospif((float)x / 511.0f);
}

// ---------------- fused table fills ----------------
// blocks 0..511: W1 (m = bid); blocks 512..1023: W3 (kb = bid - 512)
__global__ void k_fill() {
    int bid = blockIdx.x;
    if (bid < 512) {
        int m = bid;
        int k = threadIdx.x;       // 0..255
        __shared__ float s_sv;
        if (threadIdx.x == 0) {
            float sv = 0.0f;
            if (m < 511) {
                int i = (2 * m) & 255;
                float d = 0.0f;
#pragma unroll
                for (int q = 0; q < 4; q++) {
                    int x = q * 256 + i;
                    if (x < WIN) { float ww = hannf(x); d += ww * ww; }
                }
                sv = hannf(2 * m) / d;
            }
            s_sv = sv;
        }
        __syncthreads();
        const float invN = 1.0f / 1022.0f;
        float vc = 0.0f, vs = 0.0f;
        if (m < 511) {
            if (k == 0) vc = invN * s_sv;
            else {
                int r = (k * m) % 511;
                float sn, cs;
                sincospif(2.0f * (float)r / 511.0f, &sn, &cs);
                vc = 2.0f * invN * cs * s_sv;
                vs = -2.0f * invN * sn * s_sv;
            }
        }
        char* base = g_B1cat + (size_t)(m >> 7) * 8 * BLOB;
        int chunk = k >> 6, off = swz(m & 127, k & 63);
        *(unsigned short*)(base + (chunk) * BLOB + off) = hb(vc);
        *(unsigned short*)(base + (4 + chunk) * BLOB + off) = hb(vs);
    } else {
        int kb = bid - 512;
        char* base = g_B3cat + (size_t)(kb >> 7) * 16 * BLOB;
        int row = kb & 127;
        for (int n = threadIdx.x; n < 512; n += 256) {
            int j = (n * kb) % WIN;
            float sn, cs;
            sincospif((float)j / 511.0f, &sn, &cs);
            int chunk = n >> 6, off = swz(row, n & 63);
            *(unsigned short*)(base + (chunk) * BLOB + off) = hb(cs);        // Wch
            *(unsigned short*)(base + (8 + chunk) * BLOB + off) = hb(-sn);   // Wsh
        }
    }
}

// ---------------- fold1: spectrum fold, fp16 hi only ----------------
__global__ void k_fold1(const float2* __restrict__ inF2) {
    __shared__ ushort2 tile[32][33];
    int f0 = blockIdx.x * 32;    // 0..8096
    int k0 = blockIdx.y * 32;    // 0..224
    int lx = threadIdx.x & 31, ly = threadIdx.x >> 5;
    int f = f0 + lx;
    int b = f / 127, t = f - b * 127;
#pragma unroll
    for (int q = 0; q < 4; q++) {
        int k = k0 + ly + 8 * q;
        float2 x0 = inF2[(b * 512 + k) * 127 + t];
        float2 x1 = inF2[(b * 512 + 511 - k) * 127 + t];
        ushort2 v;
        v.x = hb(x0.x + x1.x);   // Arh
        v.y = hb(x0.y - x1.y);   // Aih
        tile[ly + 8 * q][lx] = v;
    }
    __syncthreads();
    char* base = g_A1cat + (size_t)(f0 >> 7) * 8 * BLOB;
    int row0 = f0 & 127;
    int kk = k0 + lx;
    int chunk = kk >> 6, col = kk & 63;
#pragma unroll
    for (int q = 0; q < 4; q++) {
        int fl = ly + 8 * q;
        ushort2 v = tile[lx][fl];
        int off = swz(row0 + fl, col);
        *(unsigned short*)(base + (chunk) * BLOB + off) = v.x;
        *(unsigned short*)(base + (4 + chunk) * BLOB + off) = v.y;
    }
}

// ---------------- GEMM 1: frames[f][m], M=128 f x N=64 m, depth-3 pipeline, 3 CTA/SM ----------------
__global__ void __launch_bounds__(256, 3) k_mma1() {
    extern __shared__ char smem[];
    uint32_t sb = smem_to_u32(smem);
    int tid = threadIdx.x, lane = tid & 31, wid = tid >> 5;
    int wm = wid >> 1, wn = wid & 1;     // 4 x 2 warps: M 32/warp, N 32/warp
    int ntile = blockIdx.x;      // m tile 0..7 (64 cols each)
    int ftile = blockIdx.y;      // f tile 0..63
    const char* Ab = g_A1cat + (size_t)ftile * 8 * BLOB;
    const char* Bb = g_B1cat + (size_t)(ntile >> 1) * 8 * BLOB;
    int halfoff = (ntile & 1) * 8192;

    float acc[2][4][4];
#pragma unroll
    for (int i = 0; i < 2; i++)
#pragma unroll
        for (int j = 0; j < 4; j++)
#pragma unroll
            for (int e = 0; e < 4; e++) acc[i][j][e] = 0.0f;

#define STAGE1(c) do { \
        uint32_t d = sb + ((c) % 3) * CH1_BYTES; \
        const char* ga = Ab + (size_t)(c) * BLOB; \
        const char* gb = Bb + (size_t)(c) * BLOB + halfoff; \
        _Pragma("unroll") \
        for (int r = 0; r < 4; r++) { \
            int e = tid + 256 * r; \
            cp16(d + e * 16, ga + e * 16); \
        } \
        _Pragma("unroll") \
        for (int r = 0; r < 2; r++) { \
            int e = tid + 256 * r; \
            cp16(d + 16384 + e * 16, gb + e * 16); \
        } \
        CP_COMMIT(); \
    } while (0)

    STAGE1(0); STAGE1(1);
    int S = 2;
    for (int c = 0; c < NCH1; c++) {
        if (S < NCH1) { STAGE1(S); S++; }
        int pend = S - 1 - c;
        if (pend >= 2) CP_WAIT(2); else if (pend == 1) CP_WAIT(1); else CP_WAIT(0);
        __syncthreads();
        uint32_t SA = sb + (c % 3) * CH1_BYTES, SB = SA + 16384;
#pragma unroll
        for (int k0 = 0; k0 < 64; k0 += 16) {
            uint32_t af[2][4], bf[2][4];
            int colu = k0 + ((lane >> 4) << 3);
#pragma unroll
            for (int i = 0; i < 2; i++) {
                int row = wm * 32 + i * 16 + (lane & 15);
                ldsm_x4(af[i][0], af[i][1], af[i][2], af[i][3], SA + swz(row, colu));
            }
#pragma unroll
            for (int j2 = 0; j2 < 2; j2++) {
                int row = wn * 32 + j2 * 16 + (lane & 15);
                ldsm_x4(bf[j2][0], bf[j2][1], bf[j2][2], bf[j2][3], SB + swz(row, colu));
            }
#pragma unroll
            for (int i = 0; i < 2; i++)
#pragma unroll
                for (int j = 0; j < 4; j++)
                    mma16816(acc[i][j], af[i], bf[j >> 1][j & 1], bf[j >> 1][(j & 1) + 2]);
        }
        __syncthreads();
    }
    int g = lane >> 2, t4 = lane & 3;
#pragma unroll
    for (int i = 0; i < 2; i++) {
        int f0 = ftile * 128 + wm * 32 + i * 16 + g;
#pragma unroll
        for (int j = 0; j < 4; j++) {
            int col = ntile * 64 + wn * 32 + j * 8 + t4 * 2;
            if (f0 < NF)
                *(__half2*)(g_frames + (size_t)f0 * 512 + col) = __floats2half2_rn(acc[i][j][0], acc[i][j][1]);
            if (f0 + 8 < NF)
                *(__half2*)(g_frames + (size_t)(f0 + 8) * 512 + col) = __floats2half2_rn(acc[i][j][2], acc[i][j][3]);
        }
    }
}

// ---------------- pass 1b: odd tail of frame 126 (rotation recurrence, 512 thr) ----------------
__global__ void k_pass1b(const float2* __restrict__ inF2) {
    __shared__ float2 sbuf[512];
    __shared__ float part[31][16];
    int b = blockIdx.x;
    int tid = threadIdx.x;   // 512 threads
    if (tid < 512)
        sbuf[tid] = inF2[(b * 512 + tid) * 127 + 126];
    __syncthreads();
    int ni = tid >> 4, kp = tid & 15;
    if (ni < 31) {
        int n = 961 + 2 * ni;
        float c, s, cs, ss;
        sincospif((float)((n * kp) % WIN) / 511.0f, &s, &c);
        sincospif((float)((16 * n) % WIN) / 511.0f, &ss, &cs);
        float acc = 0.0f;
#pragma unroll 8
        for (int it = 0; it < 32; it++) {
            float2 x = sbuf[kp + 16 * it];
            acc += 2.0f * (x.x * c - x.y * s);
            float c2 = c * cs - s * ss;
            s = c * ss + s * cs;
            c = c2;
        }
        if (kp == 0) acc -= sbuf[0].x;
        if (kp == 15) acc += sbuf[511].x;
        part[ni][kp] = acc;
    }
    __syncthreads();
    if (tid < 31) {
        float sum = 0.0f;
#pragma unroll
        for (int q = 0; q < 16; q++) sum += part[tid][q];
        int np = 961 + 2 * tid;
        int i = np & 255;
        float d = 0.0f;
#pragma unroll
        for (int q = 0; q < 4; q++) {
            int x = q * 256 + i;
            if (x < WIN) { float ww = hannf(x); d += ww * ww; }
        }
        g_tail[b * 32 + tid] = sum * (1.0f / 1022.0f) * (hannf(np) / d);
    }
}

// ---------------- pass 2: overlap-add (fp16 frame reads) ----------------
__global__ void k_pass2() {
    int idx = blockIdx.x * blockDim.x + threadIdx.x;
    if (idx >= BATCH * L_OUT) return;
    int b = idx / L_OUT, j = idx - b * L_OUT;
    float v;
    if (j < J_EVEN) {
        int p = 2 * j;
        int t_hi = min(126, p >> 8);
        int t_lo = max(0, p - 766) >> 8;
        float acc = 0.0f;
        for (int t = t_lo; t <= t_hi; t++) {
            int m = j - (t << 7);
            acc += __half2float(g_frames[(size_t)(b * 127 + t) * 512 + m]);
        }
        v = acc;
    } else {
        int n = j - 15648;
        if (n & 1) v = g_tail[b * 32 + ((n - 961) >> 1)];
        else       v = __half2float(g_frames[(size_t)(b * 127 + 126) * 512 + (n >> 1)]);
    }
    g_sig[b * SIG_STRIDE + j] = v;
}

// ---------------- fold3: window + symmetry fold, lanes along n (coalesced), no smem ----------------
__global__ void k_fold3() {
    int f0 = blockIdx.x * 32;    // 0..3936
    int n0 = blockIdx.y * 32;    // 0..480
    int lx = threadIdx.x & 31, ly = threadIdx.x >> 5;
    int n = n0 + lx;
    float w = hannf(n);
    bool hasp = (n >= 1 && n <= 510);
    char* base = g_A3cat + (size_t)(f0 >> 7) * 16 * BLOB;
    int row0 = f0 & 127;
    int chunk = n >> 6, col = n & 63;
#pragma unroll
    for (int q = 0; q < 4; q++) {
        int fl = ly + 8 * q;
        int f = f0 + fl;
        int b = f / 62, t = f - b * 62;
        int bs = b * SIG_STRIDE + t * 256;
        float y = g_sig[bs + n];
        float yp = hasp ? g_sig[bs + 1022 - n] : 0.0f;
        int off = swz(row0 + fl, col);
        *(unsigned short*)(base + (chunk) * BLOB + off) = hb(w * (y + yp));      // zeh
        *(unsigned short*)(base + (8 + chunk) * BLOB + off) = hb(w * (y - yp));  // zoh
    }
}

// ---------------- GEMM 3: S[k][f], M=128 k x N=64 f, depth-3 pipeline ----------------
__global__ void __launch_bounds__(256, 2) k_mma3(float2* __restrict__ outF2) {
    extern __shared__ char smem[];
    uint32_t sb = smem_to_u32(smem);
    int tid = threadIdx.x, lane = tid & 31, wid = tid >> 5;
    int wm = wid >> 1, wn = wid & 1;     // 4 x 2 warps
    int ftile = blockIdx.x;      // f tile 0..61 (64 frames each)
    int ktile = blockIdx.y;      // k tile 0..3
    const char* Ab = g_B3cat + (size_t)ktile * 16 * BLOB;        // W blobs: 0-7 Wch, 8-15 Wsh
    const char* Bb = g_A3cat + (size_t)(ftile >> 1) * 16 * BLOB; // z blobs: 0-7 zeh, 8-15 zoh
    int halfoff = (ftile & 1) * 8192;

    float acc[2][4][4], sv[2][4][4];
#pragma unroll
    for (int i = 0; i < 2; i++)
#pragma unroll
        for (int j = 0; j < 4; j++)
#pragma unroll
            for (int e = 0; e < 4; e++) acc[i][j][e] = 0.0f;

#define STAGE3(c) do { \
        uint32_t d = sb + ((c) % 3) * CH3_BYTES; \
        const char* ga = Ab + (size_t)(c) * BLOB; \
        const char* gb = Bb + (size_t)(c) * BLOB + halfoff; \
        _Pragma("unroll") \
        for (int r = 0; r < 4; r++) { \
            int e = tid + 256 * r; \
            cp16(d + e * 16, ga + e * 16); \
        } \
        _Pragma("unroll") \
        for (int r = 0; r < 2; r++) { \
            int e = tid + 256 * r; \
            cp16(d + 16384 + e * 16, gb + e * 16); \
        } \
        CP_COMMIT(); \
    } while (0)

    STAGE3(0); STAGE3(1);
    int S = 2;
    for (int c = 0; c < NCH3; c++) {
        if (S < NCH3) { STAGE3(S); S++; }
        int pend = S - 1 - c;
        if (pend >= 2) CP_WAIT(2); else if (pend == 1) CP_WAIT(1); else CP_WAIT(0);
        __syncthreads();
        uint32_t SA = sb + (c % 3) * CH3_BYTES, SB = SA + 16384;
#pragma unroll
        for (int k0 = 0; k0 < 64; k0 += 16) {
            uint32_t af[2][4], bf[2][4];
            int colu = k0 + ((lane >> 4) << 3);
#pragma unroll
            for (int i = 0; i < 2; i++) {
                int row = wm * 32 + i * 16 + (lane & 15);
                ldsm_x4(af[i][0], af[i][1], af[i][2], af[i][3], SA + swz(row, colu));
            }
#pragma unroll
            for (int j2 = 0; j2 < 2; j2++) {
                int row = wn * 32 + j2 * 16 + (lane & 15);
                ldsm_x4(bf[j2][0], bf[j2][1], bf[j2][2], bf[j2][3], SB + swz(row, colu));
            }
#pragma unroll
            for (int i = 0; i < 2; i++)
#pragma unroll
                for (int j = 0; j < 4; j++)
                    mma16816(acc[i][j], af[i], bf[j >> 1][j & 1], bf[j >> 1][(j & 1) + 2]);
        }
        __syncthreads();
        if (c == 7) {   // end of re chain
#pragma unroll
            for (int i = 0; i < 2; i++)
#pragma unroll
                for (int j = 0; j < 4; j++)
#pragma unroll
                    for (int e = 0; e < 4; e++) { sv[i][j][e] = acc[i][j][e]; acc[i][j][e] = 0.0f; }
        }
    }
    int g = lane >> 2, t4 = lane & 3;
#pragma unroll
    for (int i = 0; i < 2; i++) {
        int kb = ktile * 128 + wm * 32 + i * 16 + g;
#pragma unroll
        for (int j = 0; j < 4; j++) {
            int fc = ftile * 64 + wn * 32 + j * 8 + t4 * 2;
            int b0 = fc / 62, t0 = fc - b0 * 62;
            int b1 = (fc + 1) / 62, t1 = fc + 1 - b1 * 62;
            outF2[((size_t)b0 * 512 + kb) * 62 + t0] = make_float2(sv[i][j][0], acc[i][j][0]);
            outF2[((size_t)b1 * 512 + kb) * 62 + t1] = make_float2(sv[i][j][1], acc[i][j][1]);
            outF2[((size_t)b0 * 512 + kb + 8) * 62 + t0] = make_float2(sv[i][j][2], acc[i][j][2]);
            outF2[((size_t)b1 * 512 + kb + 8) * 62 + t1] = make_float2(sv[i][j][3], acc[i][j][3]);
        }
    }
}

// ---------------- stream/event infra (host objects, created once at load) ----------------
static cudaStream_t g_s1, g_s2;
static cudaEvent_t g_evFork, g_evJoin1, g_evJoin2;
namespace {
struct StreamInit {
    StreamInit() {
        cudaStreamCreateWithFlags(&g_s1, cudaStreamNonBlocking);
        cudaStreamCreateWithFlags(&g_s2, cudaStreamNonBlocking);
        cudaEventCreateWithFlags(&g_evFork, cudaEventDisableTiming);
        cudaEventCreateWithFlags(&g_evJoin1, cudaEventDisableTiming);
        cudaEventCreateWithFlags(&g_evJoin2, cudaEventDisableTiming);
    }
};
static StreamInit g_streamInit;
}

// ---------------- launch ----------------
extern "C" void kernel_launch(void* const* d_in, const int* in_sizes, int n_in,
                              void* d_out, int out_size) {
    (void)in_sizes; (void)n_in; (void)out_size;
    const float2* inF2 = (const float2*)d_in[0];
    float2* outF2 = (float2*)d_out;

    cudaFuncSetAttribute(k_mma1, cudaFuncAttributeMaxDynamicSharedMemorySize, 3 * CH1_BYTES);
    cudaFuncSetAttribute(k_mma3, cudaFuncAttributeMaxDynamicSharedMemorySize, 3 * CH3_BYTES);

    // fork: fill on s1, pass1b on s2, fold1 on main stream
    cudaEventRecord(g_evFork, 0);
    cudaStreamWaitEvent(g_s1, g_evFork, 0);
    cudaStreamWaitEvent(g_s2, g_evFork, 0);

    k_fill<<<1024, 256, 0, g_s1>>>();
    cudaEventRecord(g_evJoin1, g_s1);

    k_pass1b<<<64, 512, 0, g_s2>>>(inF2);
    cudaEventRecord(g_evJoin2, g_s2);

    k_fold1<<<dim3(254, 8), 256>>>(inF2);

    // join fill before mma1 (needs B1 tables; B3 transitively before mma3)
    cudaStreamWaitEvent(0, g_evJoin1, 0);
    k_mma1<<<dim3(8, 64), 256, 3 * CH1_BYTES>>>();

    // join pass1b before pass2 (needs g_tail)
    cudaStreamWaitEvent(0, g_evJoin2, 0);
    k_pass2<<<(BATCH * L_OUT + 255) / 256, 256>>>();
    k_fold3<<<dim3(124, 16), 256>>>();
    k_mma3<<<dim3(62, 4), 256, 3 * CH3_BYTES>>>(outF2);
}